// round 1
// baseline (speedup 1.0000x reference)
#include <cuda_runtime.h>

// EMA over time: y_t = (1-a)*y_{t-1} + a*x_t, a = 0.9, y_{-1} = 0.
// Shapes fixed by the problem: x [B=16, T=4000, C=512] fp32, out same.
//
// Because (1-a) = 0.1, influence decays by 10x per step: a warmup window of
// W=12 steps reconstructs the carry to ~1e-12 relative error, so T can be
// chunked into independent segments -> fully parallel, memory-bound kernel.

static constexpr int B = 16;
static constexpr int T = 4000;
static constexpr int C = 512;
static constexpr int C4 = C / 4;        // float4 lanes per row = 128
static constexpr int CHUNK = 125;       // T / CHUNK = 32 chunks
static constexpr int NCHUNK = T / CHUNK;
static constexpr int W = 12;            // warmup steps; 0.1^12 = 1e-12

__global__ __launch_bounds__(C4) void ema_kernel(const float4* __restrict__ x,
                                                 float4* __restrict__ y) {
    const int c4 = threadIdx.x;          // 0..127
    const int chunk = blockIdx.x;        // 0..31
    const int b = blockIdx.y;            // 0..15

    const float a = 0.9f;
    const float om = 0.1f;               // f32 round of (1.0 - 0.9) in double

    const int t0 = chunk * CHUNK;
    const int tw = (t0 >= W) ? (t0 - W) : 0;

    const size_t base = (size_t)b * T * C4 + c4;

    float4 acc = make_float4(0.f, 0.f, 0.f, 0.f);

    // Warmup: rebuild carry from W steps back (error ~0.1^W, negligible).
    #pragma unroll
    for (int t = 0; t < W; ++t) {
        int tt = tw + t;
        if (tt < t0) {
            float4 v = x[base + (size_t)tt * C4];
            acc.x = fmaf(om, acc.x, a * v.x);
            acc.y = fmaf(om, acc.y, a * v.y);
            acc.z = fmaf(om, acc.z, a * v.z);
            acc.w = fmaf(om, acc.w, a * v.w);
        }
    }

    // Main chunk: compute and store.
    size_t idx = base + (size_t)t0 * C4;
    #pragma unroll 5
    for (int t = 0; t < CHUNK; ++t) {
        float4 v = x[idx];
        acc.x = fmaf(om, acc.x, a * v.x);
        acc.y = fmaf(om, acc.y, a * v.y);
        acc.z = fmaf(om, acc.z, a * v.z);
        acc.w = fmaf(om, acc.w, a * v.w);
        y[idx] = acc;
        idx += C4;
    }
}

extern "C" void kernel_launch(void* const* d_in, const int* in_sizes, int n_in,
                              void* d_out, int out_size) {
    const float4* x = (const float4*)d_in[0];
    float4* y = (float4*)d_out;
    dim3 grid(NCHUNK, B);
    dim3 block(C4);
    ema_kernel<<<grid, block>>>(x, y);
}

// round 2
// speedup vs baseline: 1.1230x; 1.1230x over previous
#include <cuda_runtime.h>

// EMA over time: y_t = 0.1*y_{t-1} + 0.9*x_t, y_{-1} = 0.
// x [B=16, T=4000, C=512] fp32 -> y same shape.
//
// Decay is 10x per step, so a W-step warmup rebuilds the carry to 0.1^W
// relative error; chunks of T are independent -> fully parallel.
//
// R1 changes vs R0 (53.8us, DRAM 57.7%, occ 20.4%, issue 6.6%):
//  - CHUNK 125 -> 50: 1280 CTAs (~35 warps/SM) for latency hiding
//  - G=5 load batching per iteration: MLP_p1 ~ 5 per thread
//  - W 12 -> 8 (0.1^8 = 1e-8 << 1e-3 tolerance), less read amplification

static constexpr int B = 16;
static constexpr int T = 4000;
static constexpr int C = 512;
static constexpr int C4 = C / 4;        // 128 float4 lanes per (b,t) row
static constexpr int CHUNK = 50;        // 80 chunks along T
static constexpr int NCHUNK = T / CHUNK;
static constexpr int W = 8;             // warmup steps; 0.1^8 = 1e-8
static constexpr int G = 5;             // timesteps batched per inner iter

__global__ __launch_bounds__(C4) void ema_kernel(const float4* __restrict__ x,
                                                 float4* __restrict__ y) {
    const int c4 = threadIdx.x;          // 0..127
    const int chunk = blockIdx.x;        // 0..79
    const int b = blockIdx.y;            // 0..15

    const float a = 0.9f;
    const float om = 0.1f;

    const int t0 = chunk * CHUNK;
    const size_t base = (size_t)b * T * C4 + c4;

    float4 acc = make_float4(0.f, 0.f, 0.f, 0.f);

    // Warmup: rebuild carry from up to W steps back (first chunk has none).
    if (t0 >= W) {
        size_t widx = base + (size_t)(t0 - W) * C4;
        // Batch all W loads up front for MLP.
        float4 v[W];
        #pragma unroll
        for (int t = 0; t < W; ++t) v[t] = x[widx + (size_t)t * C4];
        #pragma unroll
        for (int t = 0; t < W; ++t) {
            acc.x = fmaf(om, acc.x, a * v[t].x);
            acc.y = fmaf(om, acc.y, a * v[t].y);
            acc.z = fmaf(om, acc.z, a * v[t].z);
            acc.w = fmaf(om, acc.w, a * v[t].w);
        }
    }

    // Main chunk: G-wide load batches, then serial FMA chain, then G stores.
    size_t idx = base + (size_t)t0 * C4;
    #pragma unroll 2
    for (int g = 0; g < CHUNK / G; ++g) {
        float4 v[G];
        #pragma unroll
        for (int t = 0; t < G; ++t) v[t] = x[idx + (size_t)t * C4];
        #pragma unroll
        for (int t = 0; t < G; ++t) {
            acc.x = fmaf(om, acc.x, a * v[t].x);
            acc.y = fmaf(om, acc.y, a * v[t].y);
            acc.z = fmaf(om, acc.z, a * v[t].z);
            acc.w = fmaf(om, acc.w, a * v[t].w);
            v[t] = acc;
        }
        #pragma unroll
        for (int t = 0; t < G; ++t) y[idx + (size_t)t * C4] = v[t];
        idx += (size_t)G * C4;
    }
}

extern "C" void kernel_launch(void* const* d_in, const int* in_sizes, int n_in,
                              void* d_out, int out_size) {
    const float4* x = (const float4*)d_in[0];
    float4* y = (float4*)d_out;
    dim3 grid(NCHUNK, B);
    dim3 block(C4);
    ema_kernel<<<grid, block>>>(x, y);
}